// round 5
// baseline (speedup 1.0000x reference)
#include <cuda_runtime.h>
#include <math.h>

// ---------------------------------------------------------------------------
// Problem constants
// ---------------------------------------------------------------------------
#define BB   8      // batch
#define CC   256    // dim
#define HH   40     // pooled height
#define WW   40     // pooled width
#define LL   1600   // tokens per batch (40*40)
#define LLP  1664   // padded token stride (13 * 128)
#define NH   8      // heads
#define HD   32     // head dim
#define HID  1024   // mlp hidden
#define HIRES 160   // low spatial
#define HRES  80    // high spatial

// ---------------------------------------------------------------------------
// Scratch (static __device__ globals; zero-initialized at module load).
// Tail columns [LL, LLP) of every buffer are either explicitly zeroed by the
// producers below or never written (stay 0); they are never read as valid
// output, only flow column-locally through the GEMMs (finite garbage).
// ---------------------------------------------------------------------------
__device__ float g_posT [CC * LL];
__device__ float g_resid[BB * CC * LLP];
__device__ float g_lowpe[BB * CC * LLP];
__device__ float g_highpe[BB * CC * LLP];
__device__ float g_Q[BB * CC * LLP];
__device__ float g_K[BB * CC * LLP];
__device__ float g_V[BB * CC * LLP];
__device__ float g_qscale[BB * CC];
__device__ float g_kscale[BB * CC];
__device__ float g_KV[BB * NH * HD * HD];
__device__ float g_attn[BB * CC * LLP];     // tails never written -> stay 0
__device__ float g_o[BB * CC * LLP];
__device__ float g_res2[BB * CC * LLP];     // tails never written -> stay 0
__device__ float g_h[BB * HID * LLP];
__device__ float g_m[BB * CC * LLP];
__device__ float g_final[BB * CC * LLP];

// packed fp32x2 FMA (Blackwell): d = a * b + d elementwise on 2 packed floats
__device__ __forceinline__ void ffma2(unsigned long long& d,
                                      unsigned long long a,
                                      unsigned long long b) {
    asm("fma.rn.f32x2 %0, %1, %2, %0;" : "+l"(d) : "l"(a), "l"(b));
}

// ---------------------------------------------------------------------------
// 1) Positional embedding, transposed: posT[c][l]  (stride LL)
// ---------------------------------------------------------------------------
__global__ void pos_kernel() {
    int idx = blockIdx.x * 256 + threadIdx.x;
    if (idx >= CC * LL) return;
    int c = idx / LL;
    int l = idx % LL;
    int g = c >> 6;
    int j = c & 63;
    float om  = __powf(10000.0f, -(float)j / 64.0f);
    float coord = (g < 2) ? (float)(l / WW) : (float)(l % WW);
    float arg = coord * om;
    g_posT[idx] = (g & 1) ? cosf(arg) : sinf(arg);
}

// ---------------------------------------------------------------------------
// 2) Pooling (writes padded stride, zeros the tail columns)
// ---------------------------------------------------------------------------
__global__ void pool_low_kernel(const float* __restrict__ low) {
    int bc = blockIdx.x;
    int c  = bc % CC;
    const float* src = low + (size_t)bc * HIRES * HIRES;
    for (int l = threadIdx.x; l < LLP; l += 256) {
        size_t o = (size_t)bc * LLP + l;
        if (l < LL) {
            int ih = l / WW, iw = l % WW;
            float s = 0.f;
            #pragma unroll
            for (int r = 0; r < 4; r++) {
                const float* row = src + (4 * ih + r) * HIRES + 4 * iw;
                s += row[0] + row[1] + row[2] + row[3];
            }
            float m = s * 0.0625f;
            g_resid[o] = m;
            g_lowpe[o] = m + g_posT[c * LL + l];
        } else {
            g_resid[o] = 0.f;
            g_lowpe[o] = 0.f;
        }
    }
}

__global__ void pool_high_kernel(const float* __restrict__ high) {
    int bc = blockIdx.x;
    int c  = bc % CC;
    const float* src = high + (size_t)bc * HRES * HRES;
    for (int l = threadIdx.x; l < LLP; l += 256) {
        size_t o = (size_t)bc * LLP + l;
        if (l < LL) {
            int ih = l / WW, iw = l % WW;
            const float* r0 = src + (2 * ih) * HRES + 2 * iw;
            const float* r1 = r0 + HRES;
            float m = (r0[0] + r0[1] + r1[0] + r1[1]) * 0.25f;
            g_highpe[o] = m + g_posT[c * LL + l];
        } else {
            g_highpe[o] = 0.f;
        }
    }
}

// ---------------------------------------------------------------------------
// 3) Channel-major SGEMM with packed f32x2 FMAs.
//    Y[b][m][l] = sum_k A[m][k] * X[b][k][l] + bias[m]   (EPI=1: + exact GELU)
//    Tile 128(M) x 128(N), k-step 8, 256 threads, 8x8 micro-tile,
//    A duplicated in SMEM so both FFMA2 operands load as packed 64-bit.
//    Register-staged double buffering, one __syncthreads per k-tile.
// ---------------------------------------------------------------------------
#define SD 264   // As row stride in floats (>= 256, /4)

template<int EPI, int SRC, int DST>
__global__ void __launch_bounds__(256, 2)
sgemm_cm(const float* __restrict__ A,
         const float* __restrict__ bias,
         int M, int K) {
    const float* X = (SRC == 0) ? g_lowpe :
                     (SRC == 1) ? g_highpe :
                     (SRC == 2) ? g_attn :
                     (SRC == 3) ? g_res2 : g_h;
    float* Y = (DST == 0) ? g_Q :
               (DST == 1) ? g_K :
               (DST == 2) ? g_V :
               (DST == 3) ? g_o :
               (DST == 4) ? g_h : g_m;

    __shared__ float As[2][8][SD];    // [buf][k][2*m] duplicated pairs
    __shared__ float Bs[2][8][128];   // [buf][k][n]

    int b  = blockIdx.z;
    int m0 = blockIdx.y * 128;
    int n0 = blockIdx.x * 128;
    const float* Xb = X + (size_t)b * K * LLP;
    float*       Yb = Y + (size_t)b * M * LLP;

    int tid = threadIdx.x;
    int tx = tid & 15;          // n-group (8 cols)
    int ty = tid >> 4;          // m-group (8 rows)
    int mA = tid >> 1;          // A-load: m row (0..127)
    int kA = (tid & 1) * 4;     // A-load: k quad
    int rB = tid >> 5;          // B-load: k row (0..7)
    int cB = (tid & 31) * 4;    // B-load: n quad

    const float* Aptr = A + (size_t)(m0 + mA) * K + kA;
    const float* Bptr = Xb + (size_t)rB * LLP + n0 + cB;

    unsigned long long acc[8][4];
    #pragma unroll
    for (int i = 0; i < 8; i++)
        #pragma unroll
        for (int j = 0; j < 4; j++) acc[i][j] = 0ull;

    int nt = K >> 3;

    // preload tile 0
    {
        float4 a4 = *(const float4*)(Aptr);
        float4 b4 = *(const float4*)(Bptr);
        const float* av = &a4.x;
        #pragma unroll
        for (int j = 0; j < 4; j++)
            *(float2*)&As[0][kA + j][2 * mA] = make_float2(av[j], av[j]);
        *(float4*)&Bs[0][rB][cB] = b4;
    }
    __syncthreads();

    for (int kt = 0; kt < nt; kt++) {
        int buf = kt & 1;
        float4 a4, b4;
        if (kt + 1 < nt) {
            a4 = *(const float4*)(Aptr + (kt + 1) * 8);
            b4 = *(const float4*)(Bptr + (size_t)(kt + 1) * 8 * LLP);
        }

        #pragma unroll
        for (int k = 0; k < 8; k++) {
            unsigned long long a[8], bb[4];
            #pragma unroll
            for (int ii = 0; ii < 4; ii++) {
                ulonglong2 t = *(const ulonglong2*)&As[buf][k][ty * 16 + 4 * ii];
                a[2 * ii] = t.x; a[2 * ii + 1] = t.y;
            }
            {
                ulonglong2 t0 = *(const ulonglong2*)&Bs[buf][k][tx * 8];
                ulonglong2 t1 = *(const ulonglong2*)&Bs[buf][k][tx * 8 + 4];
                bb[0] = t0.x; bb[1] = t0.y; bb[2] = t1.x; bb[3] = t1.y;
            }
            #pragma unroll
            for (int i = 0; i < 8; i++)
                #pragma unroll
                for (int j = 0; j < 4; j++)
                    ffma2(acc[i][j], a[i], bb[j]);
        }

        if (kt + 1 < nt) {
            int nb = buf ^ 1;
            const float* av = &a4.x;
            #pragma unroll
            for (int j = 0; j < 4; j++)
                *(float2*)&As[nb][kA + j][2 * mA] = make_float2(av[j], av[j]);
            *(float4*)&Bs[nb][rB][cB] = b4;
        }
        __syncthreads();
    }

    // epilogue
    #pragma unroll
    for (int i = 0; i < 8; i++) {
        int m = m0 + ty * 8 + i;
        float bsc = bias[m];
        float v[8];
        #pragma unroll
        for (int j = 0; j < 4; j++) {
            float2 p = *(float2*)&acc[i][j];
            v[2 * j]     = p.x + bsc;
            v[2 * j + 1] = p.y + bsc;
        }
        if (EPI == 1) {
            #pragma unroll
            for (int j = 0; j < 8; j++)
                v[j] = 0.5f * v[j] * (1.0f + erff(v[j] * 0.70710678118654752f));
        }
        float* yp = Yb + (size_t)m * LLP + n0 + tx * 8;
        *(float4*)yp       = make_float4(v[0], v[1], v[2], v[3]);
        *(float4*)(yp + 4) = make_float4(v[4], v[5], v[6], v[7]);
    }
}

// ---------------------------------------------------------------------------
// 4) L1-norm scales over sequence
// ---------------------------------------------------------------------------
__global__ void abssum_kernel() {
    int bc = blockIdx.x;
    const float* src = ((blockIdx.y == 0) ? g_Q : g_K) + (size_t)bc * LLP;
    float s = 0.f;
    for (int l = threadIdx.x; l < LL; l += 256) s += fabsf(src[l]);
    __shared__ float red[256];
    red[threadIdx.x] = s;
    __syncthreads();
    for (int o = 128; o > 0; o >>= 1) {
        if (threadIdx.x < o) red[threadIdx.x] += red[threadIdx.x + o];
        __syncthreads();
    }
    if (threadIdx.x == 0) {
        float sc = 1.0f / fmaxf(red[0], 1e-6f);
        ((blockIdx.y == 0) ? g_qscale : g_kscale)[bc] = sc;
    }
}

// ---------------------------------------------------------------------------
// 5) KV[n][d][m] with folded Q/K L1 normalizers
// ---------------------------------------------------------------------------
__global__ void kv_kernel() {
    int n = blockIdx.x;
    int b = n / NH, h = n % NH;
    int chbase = h * HD;
    const float* Kp = g_K + ((size_t)b * CC + chbase) * LLP;
    const float* Vp = g_V + ((size_t)b * CC + chbase) * LLP;

    __shared__ float Ks[32][33], Vs[32][33];
    int row = threadIdx.x / 32, col = threadIdx.x % 32;
    float acc = 0.f;
    for (int l0 = 0; l0 < LL; l0 += 32) {
        Ks[row][col] = Kp[(size_t)row * LLP + l0 + col];
        Vs[row][col] = Vp[(size_t)row * LLP + l0 + col];
        __syncthreads();
        #pragma unroll
        for (int lc = 0; lc < 32; lc++)
            acc = fmaf(Ks[row][lc], Vs[col][lc], acc);
        __syncthreads();
    }
    float sc = g_kscale[b * CC + chbase + row] * g_qscale[b * CC + chbase + row];
    g_KV[((size_t)n * HD + row) * HD + col] = acc * sc;
}

// ---------------------------------------------------------------------------
// 6) attn = Q @ KV, fused RMSNorm over head dim
// ---------------------------------------------------------------------------
__global__ void attn_kernel(const float* __restrict__ rms_w) {
    int n  = blockIdx.y;
    int l0 = blockIdx.x * 32;
    int b = n / NH, h = n % NH;
    int chbase = h * HD;

    __shared__ float KVs[32][33], Qs[32][33], S[32][33];
    int row = threadIdx.x / 32, col = threadIdx.x % 32;

    KVs[row][col] = g_KV[((size_t)n * HD + row) * HD + col];
    const float* Qp = g_Q + ((size_t)b * CC + chbase) * LLP;
    Qs[row][col] = Qp[(size_t)row * LLP + l0 + col];
    __syncthreads();

    float acc = 0.f;
    #pragma unroll
    for (int d = 0; d < 32; d++)
        acc = fmaf(Qs[d][col], KVs[d][row], acc);
    S[row][col] = acc;
    __syncthreads();

    float ss = 0.f;
    #pragma unroll
    for (int mm = 0; mm < 32; mm++) { float v = S[mm][col]; ss = fmaf(v, v, ss); }
    float r = rsqrtf(ss * (1.0f / 32.0f) + 1.1920929e-07f);

    g_attn[((size_t)b * CC + chbase + row) * LLP + l0 + col] = acc * r * rms_w[row];
}

// ---------------------------------------------------------------------------
// 7) Token LayerNorm + residual (column LN in channel-major layout)
// ---------------------------------------------------------------------------
template<int SRC>
__global__ void ln_res_kernel(const float* __restrict__ w, const float* __restrict__ bias) {
    const float* X = (SRC == 0) ? g_o     : g_m;
    const float* R = (SRC == 0) ? g_resid : g_res2;
    float*       Y = (SRC == 0) ? g_res2  : g_final;

    int b = blockIdx.y;
    int l = blockIdx.x * 256 + threadIdx.x;
    if (l >= LL) return;

    const float* Xb = X + (size_t)b * CC * LLP + l;
    float s = 0.f, ss = 0.f;
    for (int c = 0; c < CC; c++) {
        float v = Xb[(size_t)c * LLP];
        s += v; ss = fmaf(v, v, ss);
    }
    float mean = s * (1.0f / CC);
    float var  = ss * (1.0f / CC) - mean * mean;
    float rstd = rsqrtf(var + 1e-5f);

    const float* Rb = R + (size_t)b * CC * LLP + l;
    float*       Yb = Y + (size_t)b * CC * LLP + l;
    for (int c = 0; c < CC; c++) {
        float v = Xb[(size_t)c * LLP];
        Yb[(size_t)c * LLP] = Rb[(size_t)c * LLP] + (v - mean) * rstd * w[c] + bias[c];
    }
}

// ---------------------------------------------------------------------------
// 8) Bilinear 4x upsample (half-pixel, clamped) * original low
// ---------------------------------------------------------------------------
__global__ void resize_mul_kernel(const float* __restrict__ low, float* __restrict__ out) {
    int bc = blockIdx.x;
    __shared__ float P[LL];
    const float* Fp = g_final + (size_t)bc * LLP;
    for (int i = threadIdx.x; i < LL; i += 256) P[i] = Fp[i];
    __syncthreads();

    const float* lp = low + (size_t)bc * HIRES * HIRES;
    float*       op = out + (size_t)bc * HIRES * HIRES;
    for (int idx = threadIdx.x; idx < HIRES * HIRES; idx += 256) {
        int y = idx / HIRES, x = idx % HIRES;
        float sy = y * 0.25f - 0.375f;
        float sx = x * 0.25f - 0.375f;
        int y0 = (int)floorf(sy); float fy = sy - y0;
        int x0 = (int)floorf(sx); float fx = sx - x0;
        int y1 = min(y0 + 1, HH - 1); y0 = max(y0, 0);
        int x1 = min(x0 + 1, WW - 1); x0 = max(x0, 0);
        float v00 = P[y0 * WW + x0], v01 = P[y0 * WW + x1];
        float v10 = P[y1 * WW + x0], v11 = P[y1 * WW + x1];
        float v = v00 * (1.f - fy) * (1.f - fx) + v01 * (1.f - fy) * fx
                + v10 * fy * (1.f - fx)         + v11 * fy * fx;
        op[idx] = v * lp[idx];
    }
}

// ---------------------------------------------------------------------------
// Launch
// ---------------------------------------------------------------------------
extern "C" void kernel_launch(void* const* d_in, const int* in_sizes, int n_in,
                              void* d_out, int out_size) {
    const float* low  = (const float*)d_in[0];
    const float* high = (const float*)d_in[1];
    const float* q_w = (const float*)d_in[2];  const float* q_b = (const float*)d_in[3];
    const float* k_w = (const float*)d_in[4];  const float* k_b = (const float*)d_in[5];
    const float* v_w = (const float*)d_in[6];  const float* v_b = (const float*)d_in[7];
    const float* o_w = (const float*)d_in[8];  const float* o_b = (const float*)d_in[9];
    const float* rms_w = (const float*)d_in[10];
    const float* l1_w = (const float*)d_in[11]; const float* l1_b = (const float*)d_in[12];
    const float* l2_w = (const float*)d_in[13]; const float* l2_b = (const float*)d_in[14];
    const float* n1_w = (const float*)d_in[15]; const float* n1_b = (const float*)d_in[16];
    const float* n2_w = (const float*)d_in[17]; const float* n2_b = (const float*)d_in[18];
    float* out = (float*)d_out;

    pos_kernel<<<(CC * LL + 255) / 256, 256>>>();
    pool_low_kernel <<<BB * CC, 256>>>(low);
    pool_high_kernel<<<BB * CC, 256>>>(high);

    dim3 gP(LLP / 128, CC / 128, BB);           // 13 x 2 x 8
    sgemm_cm<0, 0, 0><<<gP, 256>>>(q_w, q_b, CC, CC);
    sgemm_cm<0, 1, 1><<<gP, 256>>>(k_w, k_b, CC, CC);
    sgemm_cm<0, 1, 2><<<gP, 256>>>(v_w, v_b, CC, CC);

    abssum_kernel<<<dim3(BB * CC, 2), 256>>>();
    kv_kernel<<<BB * NH, 1024>>>();
    attn_kernel<<<dim3(LL / 32, BB * NH), 1024>>>(rms_w);

    sgemm_cm<0, 2, 3><<<gP, 256>>>(o_w, o_b, CC, CC);
    ln_res_kernel<0><<<dim3((LL + 255) / 256, BB), 256>>>(n1_w, n1_b);

    dim3 gH(LLP / 128, HID / 128, BB);          // 13 x 8 x 8
    sgemm_cm<1, 3, 4><<<gH, 256>>>(l1_w, l1_b, HID, CC);
    sgemm_cm<0, 4, 5><<<gP, 256>>>(l2_w, l2_b, CC, HID);
    ln_res_kernel<1><<<dim3((LL + 255) / 256, BB), 256>>>(n2_w, n2_b);

    resize_mul_kernel<<<BB * CC, 256>>>(low, out);
}

// round 7
// speedup vs baseline: 1.0004x; 1.0004x over previous
#include <cuda_runtime.h>
#include <math.h>

// ---------------------------------------------------------------------------
// Problem constants
// ---------------------------------------------------------------------------
#define BB   8      // batch
#define CC   256    // dim
#define HH   40     // pooled height
#define WW   40     // pooled width
#define LL   1600   // tokens per batch (40*40)
#define LLP  1664   // padded token stride (13 * 128)
#define NH   8      // heads
#define HD   32     // head dim
#define HID  1024   // mlp hidden
#define HIRES 160   // low spatial
#define HRES  80    // high spatial

// ---------------------------------------------------------------------------
// Scratch (static __device__ globals; zero-initialized at module load).
// Tail columns [LL, LLP) of every buffer are either explicitly zeroed by the
// producers below or never written (stay 0); they are never read as valid
// output, only flow column-locally through the GEMMs (finite garbage).
// ---------------------------------------------------------------------------
__device__ float g_posT [CC * LL];
__device__ float g_resid[BB * CC * LLP];
__device__ float g_lowpe[BB * CC * LLP];
__device__ float g_highpe[BB * CC * LLP];
__device__ float g_Q[BB * CC * LLP];
__device__ float g_K[BB * CC * LLP];
__device__ float g_V[BB * CC * LLP];
__device__ float g_qscale[BB * CC];
__device__ float g_kscale[BB * CC];
__device__ float g_KV[BB * NH * HD * HD];
__device__ float g_attn[BB * CC * LLP];     // tails never written -> stay 0
__device__ float g_o[BB * CC * LLP];
__device__ float g_res2[BB * CC * LLP];     // tails never written -> stay 0
__device__ float g_h[BB * HID * LLP];
__device__ float g_m[BB * CC * LLP];
__device__ float g_final[BB * CC * LLP];

// packed fp32x2 FMA (Blackwell): d = a * b + d elementwise on 2 packed floats
__device__ __forceinline__ void ffma2(unsigned long long& d,
                                      unsigned long long a,
                                      unsigned long long b) {
    asm("fma.rn.f32x2 %0, %1, %2, %0;" : "+l"(d) : "l"(a), "l"(b));
}

// ---------------------------------------------------------------------------
// 1) Positional embedding, transposed: posT[c][l]  (stride LL)
// ---------------------------------------------------------------------------
__global__ void pos_kernel() {
    int idx = blockIdx.x * 256 + threadIdx.x;
    if (idx >= CC * LL) return;
    int c = idx / LL;
    int l = idx % LL;
    int g = c >> 6;
    int j = c & 63;
    float om  = __powf(10000.0f, -(float)j / 64.0f);
    float coord = (g < 2) ? (float)(l / WW) : (float)(l % WW);
    float arg = coord * om;
    g_posT[idx] = (g & 1) ? cosf(arg) : sinf(arg);
}

// ---------------------------------------------------------------------------
// 2) Pooling (writes padded stride, zeros the tail columns)
// ---------------------------------------------------------------------------
__global__ void pool_low_kernel(const float* __restrict__ low) {
    int bc = blockIdx.x;
    int c  = bc % CC;
    const float* src = low + (size_t)bc * HIRES * HIRES;
    for (int l = threadIdx.x; l < LLP; l += 256) {
        size_t o = (size_t)bc * LLP + l;
        if (l < LL) {
            int ih = l / WW, iw = l % WW;
            float s = 0.f;
            #pragma unroll
            for (int r = 0; r < 4; r++) {
                const float* row = src + (4 * ih + r) * HIRES + 4 * iw;
                s += row[0] + row[1] + row[2] + row[3];
            }
            float m = s * 0.0625f;
            g_resid[o] = m;
            g_lowpe[o] = m + g_posT[c * LL + l];
        } else {
            g_resid[o] = 0.f;
            g_lowpe[o] = 0.f;
        }
    }
}

__global__ void pool_high_kernel(const float* __restrict__ high) {
    int bc = blockIdx.x;
    int c  = bc % CC;
    const float* src = high + (size_t)bc * HRES * HRES;
    for (int l = threadIdx.x; l < LLP; l += 256) {
        size_t o = (size_t)bc * LLP + l;
        if (l < LL) {
            int ih = l / WW, iw = l % WW;
            const float* r0 = src + (2 * ih) * HRES + 2 * iw;
            const float* r1 = r0 + HRES;
            float m = (r0[0] + r0[1] + r1[0] + r1[1]) * 0.25f;
            g_highpe[o] = m + g_posT[c * LL + l];
        } else {
            g_highpe[o] = 0.f;
        }
    }
}

// ---------------------------------------------------------------------------
// 3) Channel-major SGEMM with packed f32x2 FMAs.
//    Y[b][m][l] = sum_k A[m][k] * X[b][k][l] + bias[m]   (EPI=1: + exact GELU)
//    Tile 128(M) x 128(N), k-step 8, 256 threads, 8x8 micro-tile,
//    A duplicated in SMEM so both FFMA2 operands load as packed 64-bit.
//    Register-staged double buffering, one __syncthreads per k-tile.
// ---------------------------------------------------------------------------
#define SD 264   // As row stride in floats (multiple of 4; 264*4B = 16B-aligned rows)

template<int EPI, int SRC, int DST>
__global__ void __launch_bounds__(256, 2)
sgemm_cm(const float* __restrict__ A,
         const float* __restrict__ bias,
         int M, int K) {
    const float* X = (SRC == 0) ? g_lowpe :
                     (SRC == 1) ? g_highpe :
                     (SRC == 2) ? g_attn :
                     (SRC == 3) ? g_res2 : g_h;
    float* Y = (DST == 0) ? g_Q :
               (DST == 1) ? g_K :
               (DST == 2) ? g_V :
               (DST == 3) ? g_o :
               (DST == 4) ? g_h : g_m;

    __shared__ float As[2][8][SD];    // [buf][k][2*m] duplicated pairs
    __shared__ float Bs[2][8][128];   // [buf][k][n]

    int b  = blockIdx.z;
    int m0 = blockIdx.y * 128;
    int n0 = blockIdx.x * 128;
    const float* Xb = X + (size_t)b * K * LLP;
    float*       Yb = Y + (size_t)b * M * LLP;

    int tid = threadIdx.x;
    int tx = tid & 15;          // n-group (8 cols)
    int ty = tid >> 4;          // m-group (8 rows)
    int mA = tid >> 1;          // A-load: m row (0..127)
    int kA = (tid & 1) * 4;     // A-load: k quad
    int rB = tid >> 5;          // B-load: k row (0..7)
    int cB = (tid & 31) * 4;    // B-load: n quad

    const float* Aptr = A + (size_t)(m0 + mA) * K + kA;
    const float* Bptr = Xb + (size_t)rB * LLP + n0 + cB;

    unsigned long long acc[8][4];
    #pragma unroll
    for (int i = 0; i < 8; i++)
        #pragma unroll
        for (int j = 0; j < 4; j++) acc[i][j] = 0ull;

    int nt = K >> 3;

    // preload tile 0
    {
        float4 a4 = *(const float4*)(Aptr);
        float4 b4 = *(const float4*)(Bptr);
        const float* av = &a4.x;
        #pragma unroll
        for (int j = 0; j < 4; j++)
            *(float2*)&As[0][kA + j][2 * mA] = make_float2(av[j], av[j]);
        *(float4*)&Bs[0][rB][cB] = b4;
    }
    __syncthreads();

    for (int kt = 0; kt < nt; kt++) {
        int buf = kt & 1;
        float4 a4, b4;
        if (kt + 1 < nt) {
            a4 = *(const float4*)(Aptr + (kt + 1) * 8);
            b4 = *(const float4*)(Bptr + (size_t)(kt + 1) * 8 * LLP);
        }

        #pragma unroll
        for (int k = 0; k < 8; k++) {
            unsigned long long a[8], bb[4];
            #pragma unroll
            for (int ii = 0; ii < 4; ii++) {
                ulonglong2 t = *(const ulonglong2*)&As[buf][k][ty * 16 + 4 * ii];
                a[2 * ii] = t.x; a[2 * ii + 1] = t.y;
            }
            {
                ulonglong2 t0 = *(const ulonglong2*)&Bs[buf][k][tx * 8];
                ulonglong2 t1 = *(const ulonglong2*)&Bs[buf][k][tx * 8 + 4];
                bb[0] = t0.x; bb[1] = t0.y; bb[2] = t1.x; bb[3] = t1.y;
            }
            #pragma unroll
            for (int i = 0; i < 8; i++)
                #pragma unroll
                for (int j = 0; j < 4; j++)
                    ffma2(acc[i][j], a[i], bb[j]);
        }

        if (kt + 1 < nt) {
            int nb = buf ^ 1;
            const float* av = &a4.x;
            #pragma unroll
            for (int j = 0; j < 4; j++)
                *(float2*)&As[nb][kA + j][2 * mA] = make_float2(av[j], av[j]);
            *(float4*)&Bs[nb][rB][cB] = b4;
        }
        __syncthreads();
    }

    // epilogue
    #pragma unroll
    for (int i = 0; i < 8; i++) {
        int m = m0 + ty * 8 + i;
        float bsc = bias[m];
        float v[8];
        #pragma unroll
        for (int j = 0; j < 4; j++) {
            float2 p = *(float2*)&acc[i][j];
            v[2 * j]     = p.x + bsc;
            v[2 * j + 1] = p.y + bsc;
        }
        if (EPI == 1) {
            #pragma unroll
            for (int j = 0; j < 8; j++)
                v[j] = 0.5f * v[j] * (1.0f + erff(v[j] * 0.70710678118654752f));
        }
        float* yp = Yb + (size_t)m * LLP + n0 + tx * 8;
        *(float4*)yp       = make_float4(v[0], v[1], v[2], v[3]);
        *(float4*)(yp + 4) = make_float4(v[4], v[5], v[6], v[7]);
    }
}

// ---------------------------------------------------------------------------
// 4) L1-norm scales over sequence
// ---------------------------------------------------------------------------
__global__ void abssum_kernel() {
    int bc = blockIdx.x;
    const float* src = ((blockIdx.y == 0) ? g_Q : g_K) + (size_t)bc * LLP;
    float s = 0.f;
    for (int l = threadIdx.x; l < LL; l += 256) s += fabsf(src[l]);
    __shared__ float red[256];
    red[threadIdx.x] = s;
    __syncthreads();
    for (int o = 128; o > 0; o >>= 1) {
        if (threadIdx.x < o) red[threadIdx.x] += red[threadIdx.x + o];
        __syncthreads();
    }
    if (threadIdx.x == 0) {
        float sc = 1.0f / fmaxf(red[0], 1e-6f);
        ((blockIdx.y == 0) ? g_qscale : g_kscale)[bc] = sc;
    }
}

// ---------------------------------------------------------------------------
// 5) KV[n][d][m] with folded Q/K L1 normalizers
// ---------------------------------------------------------------------------
__global__ void kv_kernel() {
    int n = blockIdx.x;
    int b = n / NH, h = n % NH;
    int chbase = h * HD;
    const float* Kp = g_K + ((size_t)b * CC + chbase) * LLP;
    const float* Vp = g_V + ((size_t)b * CC + chbase) * LLP;

    __shared__ float Ks[32][33], Vs[32][33];
    int row = threadIdx.x / 32, col = threadIdx.x % 32;
    float acc = 0.f;
    for (int l0 = 0; l0 < LL; l0 += 32) {
        Ks[row][col] = Kp[(size_t)row * LLP + l0 + col];
        Vs[row][col] = Vp[(size_t)row * LLP + l0 + col];
        __syncthreads();
        #pragma unroll
        for (int lc = 0; lc < 32; lc++)
            acc = fmaf(Ks[row][lc], Vs[col][lc], acc);
        __syncthreads();
    }
    float sc = g_kscale[b * CC + chbase + row] * g_qscale[b * CC + chbase + row];
    g_KV[((size_t)n * HD + row) * HD + col] = acc * sc;
}

// ---------------------------------------------------------------------------
// 6) attn = Q @ KV, fused RMSNorm over head dim
// ---------------------------------------------------------------------------
__global__ void attn_kernel(const float* __restrict__ rms_w) {
    int n  = blockIdx.y;
    int l0 = blockIdx.x * 32;
    int b = n / NH, h = n % NH;
    int chbase = h * HD;

    __shared__ float KVs[32][33], Qs[32][33], S[32][33];
    int row = threadIdx.x / 32, col = threadIdx.x % 32;

    KVs[row][col] = g_KV[((size_t)n * HD + row) * HD + col];
    const float* Qp = g_Q + ((size_t)b * CC + chbase) * LLP;
    Qs[row][col] = Qp[(size_t)row * LLP + l0 + col];
    __syncthreads();

    float acc = 0.f;
    #pragma unroll
    for (int d = 0; d < 32; d++)
        acc = fmaf(Qs[d][col], KVs[d][row], acc);
    S[row][col] = acc;
    __syncthreads();

    float ss = 0.f;
    #pragma unroll
    for (int mm = 0; mm < 32; mm++) { float v = S[mm][col]; ss = fmaf(v, v, ss); }
    float r = rsqrtf(ss * (1.0f / 32.0f) + 1.1920929e-07f);

    g_attn[((size_t)b * CC + chbase + row) * LLP + l0 + col] = acc * r * rms_w[row];
}

// ---------------------------------------------------------------------------
// 7) Token LayerNorm + residual (column LN in channel-major layout)
// ---------------------------------------------------------------------------
template<int SRC>
__global__ void ln_res_kernel(const float* __restrict__ w, const float* __restrict__ bias) {
    const float* X = (SRC == 0) ? g_o     : g_m;
    const float* R = (SRC == 0) ? g_resid : g_res2;
    float*       Y = (SRC == 0) ? g_res2  : g_final;

    int b = blockIdx.y;
    int l = blockIdx.x * 256 + threadIdx.x;
    if (l >= LL) return;

    const float* Xb = X + (size_t)b * CC * LLP + l;
    float s = 0.f, ss = 0.f;
    for (int c = 0; c < CC; c++) {
        float v = Xb[(size_t)c * LLP];
        s += v; ss = fmaf(v, v, ss);
    }
    float mean = s * (1.0f / CC);
    float var  = ss * (1.0f / CC) - mean * mean;
    float rstd = rsqrtf(var + 1e-5f);

    const float* Rb = R + (size_t)b * CC * LLP + l;
    float*       Yb = Y + (size_t)b * CC * LLP + l;
    for (int c = 0; c < CC; c++) {
        float v = Xb[(size_t)c * LLP];
        Yb[(size_t)c * LLP] = Rb[(size_t)c * LLP] + (v - mean) * rstd * w[c] + bias[c];
    }
}

// ---------------------------------------------------------------------------
// 8) Bilinear 4x upsample (half-pixel, clamped) * original low
// ---------------------------------------------------------------------------
__global__ void resize_mul_kernel(const float* __restrict__ low, float* __restrict__ out) {
    int bc = blockIdx.x;
    __shared__ float P[LL];
    const float* Fp = g_final + (size_t)bc * LLP;
    for (int i = threadIdx.x; i < LL; i += 256) P[i] = Fp[i];
    __syncthreads();

    const float* lp = low + (size_t)bc * HIRES * HIRES;
    float*       op = out + (size_t)bc * HIRES * HIRES;
    for (int idx = threadIdx.x; idx < HIRES * HIRES; idx += 256) {
        int y = idx / HIRES, x = idx % HIRES;
        float sy = y * 0.25f - 0.375f;
        float sx = x * 0.25f - 0.375f;
        int y0 = (int)floorf(sy); float fy = sy - y0;
        int x0 = (int)floorf(sx); float fx = sx - x0;
        int y1 = min(y0 + 1, HH - 1); y0 = max(y0, 0);
        int x1 = min(x0 + 1, WW - 1); x0 = max(x0, 0);
        float v00 = P[y0 * WW + x0], v01 = P[y0 * WW + x1];
        float v10 = P[y1 * WW + x0], v11 = P[y1 * WW + x1];
        float v = v00 * (1.f - fy) * (1.f - fx) + v01 * (1.f - fy) * fx
                + v10 * fy * (1.f - fx)         + v11 * fy * fx;
        op[idx] = v * lp[idx];
    }
}

// ---------------------------------------------------------------------------
// Launch
// ---------------------------------------------------------------------------
extern "C" void kernel_launch(void* const* d_in, const int* in_sizes, int n_in,
                              void* d_out, int out_size) {
    const float* low  = (const float*)d_in[0];
    const float* high = (const float*)d_in[1];
    const float* q_w = (const float*)d_in[2];  const float* q_b = (const float*)d_in[3];
    const float* k_w = (const float*)d_in[4];  const float* k_b = (const float*)d_in[5];
    const float* v_w = (const float*)d_in[6];  const float* v_b = (const float*)d_in[7];
    const float* o_w = (const float*)d_in[8];  const float* o_b = (const float*)d_in[9];
    const float* rms_w = (const float*)d_in[10];
    const float* l1_w = (const float*)d_in[11]; const float* l1_b = (const float*)d_in[12];
    const float* l2_w = (const float*)d_in[13]; const float* l2_b = (const float*)d_in[14];
    const float* n1_w = (const float*)d_in[15]; const float* n1_b = (const float*)d_in[16];
    const float* n2_w = (const float*)d_in[17]; const float* n2_b = (const float*)d_in[18];
    float* out = (float*)d_out;

    pos_kernel<<<(CC * LL + 255) / 256, 256>>>();
    pool_low_kernel <<<BB * CC, 256>>>(low);
    pool_high_kernel<<<BB * CC, 256>>>(high);

    dim3 gP(LLP / 128, CC / 128, BB);           // 13 x 2 x 8
    sgemm_cm<0, 0, 0><<<gP, 256>>>(q_w, q_b, CC, CC);
    sgemm_cm<0, 1, 1><<<gP, 256>>>(k_w, k_b, CC, CC);
    sgemm_cm<0, 1, 2><<<gP, 256>>>(v_w, v_b, CC, CC);

    abssum_kernel<<<dim3(BB * CC, 2), 256>>>();
    kv_kernel<<<BB * NH, 1024>>>();
    attn_kernel<<<dim3(LL / 32, BB * NH), 1024>>>(rms_w);

    sgemm_cm<0, 2, 3><<<gP, 256>>>(o_w, o_b, CC, CC);
    ln_res_kernel<0><<<dim3((LL + 255) / 256, BB), 256>>>(n1_w, n1_b);

    dim3 gH(LLP / 128, HID / 128, BB);          // 13 x 8 x 8
    sgemm_cm<1, 3, 4><<<gH, 256>>>(l1_w, l1_b, HID, CC);
    sgemm_cm<0, 4, 5><<<gP, 256>>>(l2_w, l2_b, CC, HID);
    ln_res_kernel<1><<<dim3((LL + 255) / 256, BB), 256>>>(n2_w, n2_b);

    resize_mul_kernel<<<BB * CC, 256>>>(low, out);
}

// round 8
// speedup vs baseline: 1.1523x; 1.1518x over previous
#include <cuda_runtime.h>
#include <math.h>

// ---------------------------------------------------------------------------
// Problem constants
// ---------------------------------------------------------------------------
#define BB   8      // batch
#define CC   256    // dim
#define HH   40     // pooled height
#define WW   40     // pooled width
#define LL   1600   // tokens per batch (40*40)
#define LLP  1664   // padded token stride (13 * 128)
#define NH   8      // heads
#define HD   32     // head dim
#define HID  1024   // mlp hidden
#define HIRES 160   // low spatial
#define HRES  80    // high spatial

// ---------------------------------------------------------------------------
// Scratch (static __device__ globals; zero-initialized at module load).
// Tail columns [LL, LLP) are zeroed by producers or never written; they are
// never read as valid output (finite garbage flows column-locally only).
// ---------------------------------------------------------------------------
__device__ float g_posT [CC * LL];
__device__ float g_resid[BB * CC * LLP];
__device__ float g_lowpe[BB * CC * LLP];
__device__ float g_highpe[BB * CC * LLP];
__device__ float g_Q[BB * CC * LLP];
__device__ float g_K[BB * CC * LLP];
__device__ float g_V[BB * CC * LLP];
__device__ float g_qscale[BB * CC];
__device__ float g_kscale[BB * CC];
__device__ float g_KV[BB * NH * HD * HD];
__device__ float g_attn[BB * CC * LLP];
__device__ float g_o[BB * CC * LLP];
__device__ float g_res2[BB * CC * LLP];
__device__ float g_h[BB * HID * LLP];
__device__ float g_m[BB * CC * LLP];
__device__ float g_final[BB * CC * LLP];

// packed fp32x2 FMA: d = a * b + d (elementwise on 2 packed floats)
__device__ __forceinline__ void ffma2(unsigned long long& d,
                                      unsigned long long a,
                                      unsigned long long b) {
    asm("fma.rn.f32x2 %0, %1, %2, %0;" : "+l"(d) : "l"(a), "l"(b));
}

// duplicate one fp32 into a packed (x,x) 64-bit pair (ALU pipe, idle per ncu)
__device__ __forceinline__ unsigned long long dup2(float x) {
    unsigned int u = __float_as_uint(x);
    unsigned long long r;
    asm("mov.b64 %0, {%1, %1};" : "=l"(r) : "r"(u));
    return r;
}

// ---------------------------------------------------------------------------
// 1) Positional embedding, transposed: posT[c][l]  (stride LL)
// ---------------------------------------------------------------------------
__global__ void pos_kernel() {
    int idx = blockIdx.x * 256 + threadIdx.x;
    if (idx >= CC * LL) return;
    int c = idx / LL;
    int l = idx % LL;
    int g = c >> 6;
    int j = c & 63;
    float om  = __powf(10000.0f, -(float)j / 64.0f);
    float coord = (g < 2) ? (float)(l / WW) : (float)(l % WW);
    float arg = coord * om;
    g_posT[idx] = (g & 1) ? cosf(arg) : sinf(arg);
}

// ---------------------------------------------------------------------------
// 2) Pooling (padded stride, zero tails)
// ---------------------------------------------------------------------------
__global__ void pool_low_kernel(const float* __restrict__ low) {
    int bc = blockIdx.x;
    int c  = bc % CC;
    const float* src = low + (size_t)bc * HIRES * HIRES;
    for (int l = threadIdx.x; l < LLP; l += 256) {
        size_t o = (size_t)bc * LLP + l;
        if (l < LL) {
            int ih = l / WW, iw = l % WW;
            float s = 0.f;
            #pragma unroll
            for (int r = 0; r < 4; r++) {
                const float* row = src + (4 * ih + r) * HIRES + 4 * iw;
                s += row[0] + row[1] + row[2] + row[3];
            }
            float m = s * 0.0625f;
            g_resid[o] = m;
            g_lowpe[o] = m + g_posT[c * LL + l];
        } else {
            g_resid[o] = 0.f;
            g_lowpe[o] = 0.f;
        }
    }
}

__global__ void pool_high_kernel(const float* __restrict__ high) {
    int bc = blockIdx.x;
    int c  = bc % CC;
    const float* src = high + (size_t)bc * HRES * HRES;
    for (int l = threadIdx.x; l < LLP; l += 256) {
        size_t o = (size_t)bc * LLP + l;
        if (l < LL) {
            int ih = l / WW, iw = l % WW;
            const float* r0 = src + (2 * ih) * HRES + 2 * iw;
            const float* r1 = r0 + HRES;
            float m = (r0[0] + r0[1] + r1[0] + r1[1]) * 0.25f;
            g_highpe[o] = m + g_posT[c * LL + l];
        } else {
            g_highpe[o] = 0.f;
        }
    }
}

// ---------------------------------------------------------------------------
// 3) Channel-major GEMM body, f32x2 FMAs, A stored UNduplicated in SMEM
//    (register dup via mov.b64 on the idle ALU pipe -> 1.0 B/FMA smem traffic)
//    Y[m][l] = sum_k A[m][k] * X[k][l] + bias[m]    (EPI=1: + exact GELU)
//    Tile 128x128, k-step 8, 256 threads, 8x8 micro-tile, double buffered.
// ---------------------------------------------------------------------------
#define SDA 132   // As row stride in floats (132*4B = 528B, 16B multiple)

template<int EPI>
__device__ __forceinline__ void gemm_body(
    const float* __restrict__ A, const float* __restrict__ bias,
    const float* __restrict__ Xb, float* __restrict__ Yb,
    int K, int m0, int n0,
    float (*As)[8][SDA], float (*Bs)[8][128])
{
    int tid = threadIdx.x;
    int tx = tid & 15;          // n-group (8 cols)
    int ty = tid >> 4;          // m-group (8 rows)
    int mA = tid >> 1;          // A-load: m row (0..127)
    int kA = (tid & 1) * 4;     // A-load: k quad (0 or 4)
    int rB = tid >> 5;          // B-load: k row (0..7)
    int cB = (tid & 31) * 4;    // B-load: n quad

    const float* Aptr = A + (size_t)(m0 + mA) * K + kA;
    const float* Bptr = Xb + (size_t)rB * LLP + n0 + cB;

    unsigned long long acc[8][4];
    #pragma unroll
    for (int i = 0; i < 8; i++)
        #pragma unroll
        for (int j = 0; j < 4; j++) acc[i][j] = 0ull;

    int nt = K >> 3;

    // preload tile 0
    {
        float4 a4 = *(const float4*)(Aptr);
        float4 b4 = *(const float4*)(Bptr);
        As[0][kA + 0][mA] = a4.x;
        As[0][kA + 1][mA] = a4.y;
        As[0][kA + 2][mA] = a4.z;
        As[0][kA + 3][mA] = a4.w;
        *(float4*)&Bs[0][rB][cB] = b4;
    }
    __syncthreads();

    for (int kt = 0; kt < nt; kt++) {
        int buf = kt & 1;
        float4 a4, b4;
        if (kt + 1 < nt) {
            a4 = *(const float4*)(Aptr + (kt + 1) * 8);
            b4 = *(const float4*)(Bptr + (size_t)(kt + 1) * 8 * LLP);
        }

        #pragma unroll
        for (int k = 0; k < 8; k++) {
            // A: 2x LDS.128 natural, then dup to packed pairs on ALU pipe
            float4 av0 = *(const float4*)&As[buf][k][ty * 8];
            float4 av1 = *(const float4*)&As[buf][k][ty * 8 + 4];
            unsigned long long a[8];
            a[0] = dup2(av0.x); a[1] = dup2(av0.y);
            a[2] = dup2(av0.z); a[3] = dup2(av0.w);
            a[4] = dup2(av1.x); a[5] = dup2(av1.y);
            a[6] = dup2(av1.z); a[7] = dup2(av1.w);
            // B: 2x LDS.128, naturally packed n-pairs
            unsigned long long bb[4];
            {
                ulonglong2 t0 = *(const ulonglong2*)&Bs[buf][k][tx * 8];
                ulonglong2 t1 = *(const ulonglong2*)&Bs[buf][k][tx * 8 + 4];
                bb[0] = t0.x; bb[1] = t0.y; bb[2] = t1.x; bb[3] = t1.y;
            }
            #pragma unroll
            for (int i = 0; i < 8; i++)
                #pragma unroll
                for (int j = 0; j < 4; j++)
                    ffma2(acc[i][j], a[i], bb[j]);
        }

        if (kt + 1 < nt) {
            int nb = buf ^ 1;
            As[nb][kA + 0][mA] = a4.x;
            As[nb][kA + 1][mA] = a4.y;
            As[nb][kA + 2][mA] = a4.z;
            As[nb][kA + 3][mA] = a4.w;
            *(float4*)&Bs[nb][rB][cB] = b4;
        }
        __syncthreads();
    }

    // epilogue
    #pragma unroll
    for (int i = 0; i < 8; i++) {
        int m = m0 + ty * 8 + i;
        float bsc = bias[m];
        float v[8];
        #pragma unroll
        for (int j = 0; j < 4; j++) {
            float2 p = *(float2*)&acc[i][j];
            v[2 * j]     = p.x + bsc;
            v[2 * j + 1] = p.y + bsc;
        }
        if (EPI == 1) {
            #pragma unroll
            for (int j = 0; j < 8; j++)
                v[j] = 0.5f * v[j] * (1.0f + erff(v[j] * 0.70710678118654752f));
        }
        float* yp = Yb + (size_t)m * LLP + n0 + tx * 8;
        *(float4*)yp       = make_float4(v[0], v[1], v[2], v[3]);
        *(float4*)(yp + 4) = make_float4(v[4], v[5], v[6], v[7]);
    }
}

// Fused Q/K/V projections: gridDim.z = 3*BB (sel = z/BB, b = z%BB)
__global__ void __launch_bounds__(256, 2)
qkv_kernel(const float* __restrict__ qw, const float* __restrict__ qb,
           const float* __restrict__ kw, const float* __restrict__ kb,
           const float* __restrict__ vw, const float* __restrict__ vb) {
    __shared__ float As[2][8][SDA];
    __shared__ float Bs[2][8][128];
    int sel = blockIdx.z / BB;
    int b   = blockIdx.z % BB;
    const float* A    = (sel == 0) ? qw : (sel == 1) ? kw : vw;
    const float* bias = (sel == 0) ? qb : (sel == 1) ? kb : vb;
    const float* Xb = ((sel == 0) ? g_lowpe : g_highpe) + (size_t)b * CC * LLP;
    float* Yb = ((sel == 0) ? g_Q : (sel == 1) ? g_K : g_V) + (size_t)b * CC * LLP;
    gemm_body<0>(A, bias, Xb, Yb, CC, blockIdx.y * 128, blockIdx.x * 128, As, Bs);
}

// Generic single GEMM (O-proj, MLP1 w/ GELU, MLP2)
template<int EPI, int SRC, int DST>
__global__ void __launch_bounds__(256, 2)
sgemm_cm(const float* __restrict__ A, const float* __restrict__ bias,
         int M, int K) {
    __shared__ float As[2][8][SDA];
    __shared__ float Bs[2][8][128];
    const float* X = (SRC == 2) ? g_attn :
                     (SRC == 3) ? g_res2 : g_h;
    float* Y = (DST == 3) ? g_o :
               (DST == 4) ? g_h : g_m;
    int b = blockIdx.z;
    gemm_body<EPI>(A, bias,
                   X + (size_t)b * K * LLP,
                   Y + (size_t)b * M * LLP,
                   K, blockIdx.y * 128, blockIdx.x * 128, As, Bs);
    (void)M;
}

// ---------------------------------------------------------------------------
// 4) L1-norm scales over sequence
// ---------------------------------------------------------------------------
__global__ void abssum_kernel() {
    int bc = blockIdx.x;
    const float* src = ((blockIdx.y == 0) ? g_Q : g_K) + (size_t)bc * LLP;
    float s = 0.f;
    for (int l = threadIdx.x; l < LL; l += 256) s += fabsf(src[l]);
    __shared__ float red[256];
    red[threadIdx.x] = s;
    __syncthreads();
    for (int o = 128; o > 0; o >>= 1) {
        if (threadIdx.x < o) red[threadIdx.x] += red[threadIdx.x + o];
        __syncthreads();
    }
    if (threadIdx.x == 0) {
        float sc = 1.0f / fmaxf(red[0], 1e-6f);
        ((blockIdx.y == 0) ? g_qscale : g_kscale)[bc] = sc;
    }
}

// ---------------------------------------------------------------------------
// 5) KV[n][d][m] with folded Q/K L1 normalizers
// ---------------------------------------------------------------------------
__global__ void kv_kernel() {
    int n = blockIdx.x;
    int b = n / NH, h = n % NH;
    int chbase = h * HD;
    const float* Kp = g_K + ((size_t)b * CC + chbase) * LLP;
    const float* Vp = g_V + ((size_t)b * CC + chbase) * LLP;

    __shared__ float Ks[32][33], Vs[32][33];
    int row = threadIdx.x / 32, col = threadIdx.x % 32;
    float acc = 0.f;
    for (int l0 = 0; l0 < LL; l0 += 32) {
        Ks[row][col] = Kp[(size_t)row * LLP + l0 + col];
        Vs[row][col] = Vp[(size_t)row * LLP + l0 + col];
        __syncthreads();
        #pragma unroll
        for (int lc = 0; lc < 32; lc++)
            acc = fmaf(Ks[row][lc], Vs[col][lc], acc);
        __syncthreads();
    }
    float sc = g_kscale[b * CC + chbase + row] * g_qscale[b * CC + chbase + row];
    g_KV[((size_t)n * HD + row) * HD + col] = acc * sc;
}

// ---------------------------------------------------------------------------
// 6) attn = Q @ KV, fused RMSNorm over head dim
// ---------------------------------------------------------------------------
__global__ void attn_kernel(const float* __restrict__ rms_w) {
    int n  = blockIdx.y;
    int l0 = blockIdx.x * 32;
    int b = n / NH, h = n % NH;
    int chbase = h * HD;

    __shared__ float KVs[32][33], Qs[32][33], S[32][33];
    int row = threadIdx.x / 32, col = threadIdx.x % 32;

    KVs[row][col] = g_KV[((size_t)n * HD + row) * HD + col];
    const float* Qp = g_Q + ((size_t)b * CC + chbase) * LLP;
    Qs[row][col] = Qp[(size_t)row * LLP + l0 + col];
    __syncthreads();

    float acc = 0.f;
    #pragma unroll
    for (int d = 0; d < 32; d++)
        acc = fmaf(Qs[d][col], KVs[d][row], acc);
    S[row][col] = acc;
    __syncthreads();

    float ss = 0.f;
    #pragma unroll
    for (int mm = 0; mm < 32; mm++) { float v = S[mm][col]; ss = fmaf(v, v, ss); }
    float r = rsqrtf(ss * (1.0f / 32.0f) + 1.1920929e-07f);

    g_attn[((size_t)b * CC + chbase + row) * LLP + l0 + col] = acc * r * rms_w[row];
}

// ---------------------------------------------------------------------------
// 7) Token LayerNorm + residual (column LN in channel-major layout)
// ---------------------------------------------------------------------------
template<int SRC>
__global__ void ln_res_kernel(const float* __restrict__ w, const float* __restrict__ bias) {
    const float* X = (SRC == 0) ? g_o     : g_m;
    const float* R = (SRC == 0) ? g_resid : g_res2;
    float*       Y = (SRC == 0) ? g_res2  : g_final;

    int b = blockIdx.y;
    int l = blockIdx.x * 256 + threadIdx.x;
    if (l >= LL) return;

    const float* Xb = X + (size_t)b * CC * LLP + l;
    float s = 0.f, ss = 0.f;
    for (int c = 0; c < CC; c++) {
        float v = Xb[(size_t)c * LLP];
        s += v; ss = fmaf(v, v, ss);
    }
    float mean = s * (1.0f / CC);
    float var  = ss * (1.0f / CC) - mean * mean;
    float rstd = rsqrtf(var + 1e-5f);

    const float* Rb = R + (size_t)b * CC * LLP + l;
    float*       Yb = Y + (size_t)b * CC * LLP + l;
    for (int c = 0; c < CC; c++) {
        float v = Xb[(size_t)c * LLP];
        Yb[(size_t)c * LLP] = Rb[(size_t)c * LLP] + (v - mean) * rstd * w[c] + bias[c];
    }
}

// ---------------------------------------------------------------------------
// 8) Bilinear 4x upsample (half-pixel, clamped) * original low
// ---------------------------------------------------------------------------
__global__ void resize_mul_kernel(const float* __restrict__ low, float* __restrict__ out) {
    int bc = blockIdx.x;
    __shared__ float P[LL];
    const float* Fp = g_final + (size_t)bc * LLP;
    for (int i = threadIdx.x; i < LL; i += 256) P[i] = Fp[i];
    __syncthreads();

    const float* lp = low + (size_t)bc * HIRES * HIRES;
    float*       op = out + (size_t)bc * HIRES * HIRES;
    for (int idx = threadIdx.x; idx < HIRES * HIRES; idx += 256) {
        int y = idx / HIRES, x = idx % HIRES;
        float sy = y * 0.25f - 0.375f;
        float sx = x * 0.25f - 0.375f;
        int y0 = (int)floorf(sy); float fy = sy - y0;
        int x0 = (int)floorf(sx); float fx = sx - x0;
        int y1 = min(y0 + 1, HH - 1); y0 = max(y0, 0);
        int x1 = min(x0 + 1, WW - 1); x0 = max(x0, 0);
        float v00 = P[y0 * WW + x0], v01 = P[y0 * WW + x1];
        float v10 = P[y1 * WW + x0], v11 = P[y1 * WW + x1];
        float v = v00 * (1.f - fy) * (1.f - fx) + v01 * (1.f - fy) * fx
                + v10 * fy * (1.f - fx)         + v11 * fy * fx;
        op[idx] = v * lp[idx];
    }
}

// ---------------------------------------------------------------------------
// Launch
// ---------------------------------------------------------------------------
extern "C" void kernel_launch(void* const* d_in, const int* in_sizes, int n_in,
                              void* d_out, int out_size) {
    const float* low  = (const float*)d_in[0];
    const float* high = (const float*)d_in[1];
    const float* q_w = (const float*)d_in[2];  const float* q_b = (const float*)d_in[3];
    const float* k_w = (const float*)d_in[4];  const float* k_b = (const float*)d_in[5];
    const float* v_w = (const float*)d_in[6];  const float* v_b = (const float*)d_in[7];
    const float* o_w = (const float*)d_in[8];  const float* o_b = (const float*)d_in[9];
    const float* rms_w = (const float*)d_in[10];
    const float* l1_w = (const float*)d_in[11]; const float* l1_b = (const float*)d_in[12];
    const float* l2_w = (const float*)d_in[13]; const float* l2_b = (const float*)d_in[14];
    const float* n1_w = (const float*)d_in[15]; const float* n1_b = (const float*)d_in[16];
    const float* n2_w = (const float*)d_in[17]; const float* n2_b = (const float*)d_in[18];
    float* out = (float*)d_out;

    pos_kernel<<<(CC * LL + 255) / 256, 256>>>();
    pool_low_kernel <<<BB * CC, 256>>>(low);
    pool_high_kernel<<<BB * CC, 256>>>(high);

    // Fused Q/K/V: 13 x 2 x 24 = 624 CTAs in one launch (better wave packing)
    dim3 gQKV(LLP / 128, CC / 128, 3 * BB);
    qkv_kernel<<<gQKV, 256>>>(q_w, q_b, k_w, k_b, v_w, v_b);

    abssum_kernel<<<dim3(BB * CC, 2), 256>>>();
    kv_kernel<<<BB * NH, 1024>>>();
    attn_kernel<<<dim3(LL / 32, BB * NH), 1024>>>(rms_w);

    dim3 gP(LLP / 128, CC / 128, BB);           // 13 x 2 x 8
    sgemm_cm<0, 2, 3><<<gP, 256>>>(o_w, o_b, CC, CC);
    ln_res_kernel<0><<<dim3((LL + 255) / 256, BB), 256>>>(n1_w, n1_b);

    dim3 gH(LLP / 128, HID / 128, BB);          // 13 x 8 x 8
    sgemm_cm<1, 3, 4><<<gH, 256>>>(l1_w, l1_b, HID, CC);
    sgemm_cm<0, 4, 5><<<gP, 256>>>(l2_w, l2_b, CC, HID);
    ln_res_kernel<1><<<dim3((LL + 255) / 256, BB), 256>>>(n2_w, n2_b);

    resize_mul_kernel<<<BB * CC, 256>>>(low, out);
}